// round 7
// baseline (speedup 1.0000x reference)
#include <cuda_runtime.h>
#include <cuda_bf16.h>
#include <cuda_fp16.h>
#include <cstdint>

#define N_NODES  50000
#define N_EDGES  800000
#define HID      128
#define N_GRAPHS 512

// ---------------- scratch ----------------
__device__ int   g_deg[N_NODES];
__device__ int   g_tmp_incl[N_NODES];
__device__ int   g_bsum[64];
__device__ int   g_cursor[N_NODES];
__device__ int   g_row_start[N_NODES + 1];
__device__ int   g_counts[N_GRAPHS];
__device__ int   g_csr_src[N_EDGES];
__device__ float g_inv_deg[N_NODES];

__device__ __half g_ylh[(size_t)N_NODES * 128];   // left-branch product, fp16 (gathered)
__device__ float  g_yr[(size_t)N_NODES * 128];    // right-branch product, fp32 (own row)
__device__ float  g_h0[(size_t)N_NODES * HID];    // fp32 activations
__device__ float  g_h1[(size_t)N_NODES * HID];
// converted weights: [layer][256 rows (Wl then Wr)][128 k]
__device__ __nv_bfloat16 g_whi[3 * 256 * 128];
__device__ __nv_bfloat16 g_wlo[3 * 256 * 128];

// ---------------- split helpers ----------------
__device__ __forceinline__ void split1(float v, __nv_bfloat16& hi, __nv_bfloat16& lo) {
    hi = __float2bfloat16_rn(v);
    lo = __float2bfloat16_rn(v - __bfloat162float(hi));
}
__device__ __forceinline__ void split_pack4(float4 v, uint2& hi, uint2& lo) {
    __nv_bfloat16 hx, hy, hz, hw, lx, ly, lz, lw;
    split1(v.x, hx, lx); split1(v.y, hy, ly); split1(v.z, hz, lz); split1(v.w, hw, lw);
    hi.x = ((uint32_t)__bfloat16_as_ushort(hy) << 16) | __bfloat16_as_ushort(hx);
    hi.y = ((uint32_t)__bfloat16_as_ushort(hw) << 16) | __bfloat16_as_ushort(hz);
    lo.x = ((uint32_t)__bfloat16_as_ushort(ly) << 16) | __bfloat16_as_ushort(lx);
    lo.y = ((uint32_t)__bfloat16_as_ushort(lw) << 16) | __bfloat16_as_ushort(lz);
}

// ---------------- init: zero deg/counts/pooled + convert weights ----------------
__global__ void init_kernel(float* __restrict__ pooled,
                            const float* __restrict__ W1l, const float* __restrict__ W1r,
                            const float* __restrict__ W2l, const float* __restrict__ W2r,
                            const float* __restrict__ W3l, const float* __restrict__ W3r) {
    int i = blockIdx.x * blockDim.x + threadIdx.x;
    int stride = gridDim.x * blockDim.x;
    for (int j = i; j < N_NODES; j += stride) g_deg[j] = 0;
    for (int j = i; j < N_GRAPHS; j += stride) g_counts[j] = 0;
    for (int j = i; j < N_GRAPHS * HID; j += stride) pooled[j] = 0.0f;
    for (int idx = i; idx < 3 * 256 * 128; idx += stride) {
        int layer = idx / (256 * 128);
        int rem = idx % (256 * 128);
        int n = rem / 128, k = rem % 128;
        const float* Wp;
        if (layer == 0) Wp = (n < 128) ? W1l : W1r;
        else if (layer == 1) Wp = (n < 128) ? W2l : W2r;
        else Wp = (n < 128) ? W3l : W3r;
        float v = Wp[(n & 127) * 128 + k];
        __nv_bfloat16 hi, lo;
        split1(v, hi, lo);
        g_whi[idx] = hi;
        g_wlo[idx] = lo;
    }
}

// ---------------- histograms ----------------
__global__ void hist_kernel(const int* __restrict__ ei, const int* __restrict__ batch) {
    int e = blockIdx.x * blockDim.x + threadIdx.x;
    if (e < N_EDGES) atomicAdd(&g_deg[ei[N_EDGES + e]], 1);
    if (e < N_NODES) atomicAdd(&g_counts[batch[e]], 1);
}

// ---------------- scan A: per-block inclusive scans of deg ----------------
__global__ __launch_bounds__(1024)
void scanA_kernel() {
    __shared__ int wsum[32];
    const int t = threadIdx.x, lane = t & 31, wid = t >> 5;
    const int i = blockIdx.x * 1024 + t;
    int v = (i < N_NODES) ? g_deg[i] : 0;
    int x = v;
#pragma unroll
    for (int o = 1; o < 32; o <<= 1) {
        int y = __shfl_up_sync(0xffffffffu, x, o);
        if (lane >= o) x += y;
    }
    if (lane == 31) wsum[wid] = x;
    __syncthreads();
    if (wid == 0) {
        int w = wsum[lane];
#pragma unroll
        for (int o = 1; o < 32; o <<= 1) {
            int y = __shfl_up_sync(0xffffffffu, w, o);
            if (lane >= o) w += y;
        }
        wsum[lane] = w;
    }
    __syncthreads();
    int incl = x + (wid ? wsum[wid - 1] : 0);
    if (i < N_NODES) g_tmp_incl[i] = incl;
    if (t == 1023) g_bsum[blockIdx.x] = incl;
}

// ---------------- scan C: redundant block-sum scan + finalize row_start/cursor/inv_deg ----------------
__global__ __launch_bounds__(1024)
void scanC_kernel(int nblocks) {
    __shared__ int s[64];
    const int t = threadIdx.x;
    if (t < 64) s[t] = (t < nblocks) ? g_bsum[t] : 0;
    __syncthreads();
    // Hillis-Steele inclusive scan of 64 entries (threads 0-63)
#pragma unroll
    for (int o = 1; o < 64; o <<= 1) {
        int v = 0;
        if (t < 64 && t >= o) v = s[t - o];
        __syncthreads();
        if (t < 64) s[t] += v;
        __syncthreads();
    }
    const int i = blockIdx.x * 1024 + t;
    if (i >= N_NODES) return;
    int boff = blockIdx.x ? s[blockIdx.x - 1] : 0;   // exclusive offset for this block
    int d = g_deg[i];
    int rs = boff + g_tmp_incl[i] - d;
    g_row_start[i] = rs;
    g_cursor[i]    = rs;
    g_inv_deg[i]   = 1.0f / fmaxf((float)d, 1.0f);
    if (i == N_NODES - 1) g_row_start[N_NODES] = rs + d;
}

// ---------------- CSR fill ----------------
__global__ void csr_kernel(const int* __restrict__ ei) {
    int e = blockIdx.x * blockDim.x + threadIdx.x;
    if (e >= N_EDGES) return;
    int d = ei[N_EDGES + e];
    int p = atomicAdd(&g_cursor[d], 1);
    g_csr_src[p] = ei[e];
}

// ---------------- mma.sync bf16 GEMM: [yl(fp16) | yr(fp32)] = A(fp32) @ [Wl^T | Wr^T] ----------------
// bf16x2 split (applied during staging): D = Ahi@Bhi + Ahi@Blo + Alo@Bhi (fp32 accum)
#define ASTR 136                       // smem row stride in bf16 elems (conflict-free)
static const int SM_AHI = 0;
static const int SM_ALO = SM_AHI + 128 * ASTR * 2;   // 34816
static const int SM_BHI = SM_ALO + 128 * ASTR * 2;   // 69632
static const int SM_BLO = SM_BHI + 256 * ASTR * 2;   // 139264
static const int SM_TOT = SM_BLO + 256 * ASTR * 2;   // 208896

__device__ __forceinline__ void mma16816(float* c, const uint32_t* a, const uint32_t* b) {
    asm volatile(
        "mma.sync.aligned.m16n8k16.row.col.f32.bf16.bf16.f32 "
        "{%0,%1,%2,%3}, {%4,%5,%6,%7}, {%8,%9}, {%0,%1,%2,%3};"
        : "+f"(c[0]), "+f"(c[1]), "+f"(c[2]), "+f"(c[3])
        : "r"(a[0]), "r"(a[1]), "r"(a[2]), "r"(a[3]), "r"(b[0]), "r"(b[1]));
}

__global__ __launch_bounds__(256, 1)
void gemm_tc_kernel(const float* __restrict__ A,
                    const __nv_bfloat16* __restrict__ Whi, const __nv_bfloat16* __restrict__ Wlo) {
    extern __shared__ char smem[];
    const int t = threadIdx.x;
    const int row0 = blockIdx.x * 128;

    // ---- stage A: fp32 -> bf16 hi/lo split during staging ----
#pragma unroll
    for (int i = t; i < 128 * 32; i += 256) {
        int r = i >> 5, k = (i & 31) * 4;
        int row = row0 + r;
        float4 v = make_float4(0.f, 0.f, 0.f, 0.f);
        if (row < N_NODES) v = *reinterpret_cast<const float4*>(&A[(size_t)row * HID + k]);
        uint2 hi, lo;
        split_pack4(v, hi, lo);
        *reinterpret_cast<uint2*>(smem + SM_AHI + (r * ASTR + k) * 2) = hi;
        *reinterpret_cast<uint2*>(smem + SM_ALO + (r * ASTR + k) * 2) = lo;
    }
    // ---- stage B (256x128 bf16 hi/lo, preconverted) ----
#pragma unroll
    for (int i = t; i < 256 * 16; i += 256) {
        int n = i >> 4, k = (i & 15) * 8;
        *reinterpret_cast<uint4*>(smem + SM_BHI + (n * ASTR + k) * 2) =
            *reinterpret_cast<const uint4*>(&Whi[n * HID + k]);
        *reinterpret_cast<uint4*>(smem + SM_BLO + (n * ASTR + k) * 2) =
            *reinterpret_cast<const uint4*>(&Wlo[n * HID + k]);
    }
    __syncthreads();

    const int wid = t >> 5, lane = t & 31;
    const int g = lane >> 2, tig = lane & 3;
    const int wm = (wid & 1) * 64;        // warp M offset (2 warps in M)
    const int wn = (wid >> 1) * 64;       // warp N offset (4 warps in N)

    float acc[4][8][4];
#pragma unroll
    for (int a = 0; a < 4; a++)
#pragma unroll
        for (int b = 0; b < 8; b++)
#pragma unroll
            for (int c = 0; c < 4; c++) acc[a][b][c] = 0.0f;

    for (int ks = 0; ks < 8; ks++) {
        const int k0 = ks * 16 + tig * 2;
        uint32_t ah[4][4], al[4][4];
#pragma unroll
        for (int mt = 0; mt < 4; mt++) {
            int base = ((wm + mt * 16 + g) * ASTR + k0) * 2;
            ah[mt][0] = *reinterpret_cast<const uint32_t*>(smem + SM_AHI + base);
            ah[mt][1] = *reinterpret_cast<const uint32_t*>(smem + SM_AHI + base + 8 * ASTR * 2);
            ah[mt][2] = *reinterpret_cast<const uint32_t*>(smem + SM_AHI + base + 16);
            ah[mt][3] = *reinterpret_cast<const uint32_t*>(smem + SM_AHI + base + 8 * ASTR * 2 + 16);
            al[mt][0] = *reinterpret_cast<const uint32_t*>(smem + SM_ALO + base);
            al[mt][1] = *reinterpret_cast<const uint32_t*>(smem + SM_ALO + base + 8 * ASTR * 2);
            al[mt][2] = *reinterpret_cast<const uint32_t*>(smem + SM_ALO + base + 16);
            al[mt][3] = *reinterpret_cast<const uint32_t*>(smem + SM_ALO + base + 8 * ASTR * 2 + 16);
        }
#pragma unroll
        for (int nh = 0; nh < 2; nh++) {
            uint32_t bh[4][2], bl[4][2];
#pragma unroll
            for (int nt = 0; nt < 4; nt++) {
                int base = ((wn + nh * 32 + nt * 8 + g) * ASTR + k0) * 2;
                bh[nt][0] = *reinterpret_cast<const uint32_t*>(smem + SM_BHI + base);
                bh[nt][1] = *reinterpret_cast<const uint32_t*>(smem + SM_BHI + base + 16);
                bl[nt][0] = *reinterpret_cast<const uint32_t*>(smem + SM_BLO + base);
                bl[nt][1] = *reinterpret_cast<const uint32_t*>(smem + SM_BLO + base + 16);
            }
#pragma unroll
            for (int mt = 0; mt < 4; mt++)
#pragma unroll
                for (int nt = 0; nt < 4; nt++) {
                    float* c = acc[mt][nh * 4 + nt];
                    mma16816(c, ah[mt], bh[nt]);
                    mma16816(c, ah[mt], bl[nt]);
                    mma16816(c, al[mt], bh[nt]);
                }
        }
    }

    // ---- epilogue: cols [0,128) -> fp16 g_ylh ; cols [128,256) -> fp32 g_yr ----
#pragma unroll
    for (int mt = 0; mt < 4; mt++)
#pragma unroll
        for (int nt = 0; nt < 8; nt++) {
            int row = row0 + wm + mt * 16 + g;
            int col = wn + nt * 8 + tig * 2;
            float* c = acc[mt][nt];
            if (col < 128) {
                if (row < N_NODES)
                    *reinterpret_cast<__half2*>(&g_ylh[(size_t)row * 128 + col]) =
                        __floats2half2_rn(c[0], c[1]);
                if (row + 8 < N_NODES)
                    *reinterpret_cast<__half2*>(&g_ylh[(size_t)(row + 8) * 128 + col]) =
                        __floats2half2_rn(c[2], c[3]);
            } else {
                int cr = col - 128;
                if (row < N_NODES)
                    *reinterpret_cast<float2*>(&g_yr[(size_t)row * 128 + cr]) = make_float2(c[0], c[1]);
                if (row + 8 < N_NODES)
                    *reinterpret_cast<float2*>(&g_yr[(size_t)(row + 8) * 128 + cr]) = make_float2(c[2], c[3]);
            }
        }
}

// ---------------- combine: 16 lanes/node, LDG.128 gathers ----------------
__device__ __forceinline__ void acc_half8(float* a, uint4 u) {
    float2 f0 = __half22float2(*reinterpret_cast<__half2*>(&u.x));
    float2 f1 = __half22float2(*reinterpret_cast<__half2*>(&u.y));
    float2 f2 = __half22float2(*reinterpret_cast<__half2*>(&u.z));
    float2 f3 = __half22float2(*reinterpret_cast<__half2*>(&u.w));
    a[0] += f0.x; a[1] += f0.y; a[2] += f1.x; a[3] += f1.y;
    a[4] += f2.x; a[5] += f2.y; a[6] += f3.x; a[7] += f3.y;
}

__global__ __launch_bounds__(256)
void combine_kernel(const float* __restrict__ bias, float* __restrict__ Hout,
                    const int* __restrict__ batch, float* __restrict__ pooled,
                    int do_pool) {
    int i = (blockIdx.x * blockDim.x + threadIdx.x) >> 4;    // node (16 lanes each)
    if (i >= N_NODES) return;
    const int l = threadIdx.x & 15;
    const int co = l * 8;                                    // channel offset
    int e0 = g_row_start[i], e1 = g_row_start[i + 1];
    float a[8] = {0, 0, 0, 0, 0, 0, 0, 0};
    float b[8] = {0, 0, 0, 0, 0, 0, 0, 0};
    int e = e0;
    for (; e + 2 <= e1; e += 2) {
        int s0 = g_csr_src[e], s1 = g_csr_src[e + 1];
        acc_half8(a, *reinterpret_cast<const uint4*>(&g_ylh[(size_t)s0 * 128 + co]));
        acc_half8(b, *reinterpret_cast<const uint4*>(&g_ylh[(size_t)s1 * 128 + co]));
    }
    if (e < e1) {
        int s0 = g_csr_src[e];
        acc_half8(a, *reinterpret_cast<const uint4*>(&g_ylh[(size_t)s0 * 128 + co]));
    }
    float inv = g_inv_deg[i];
    float4 yr0 = *reinterpret_cast<const float4*>(&g_yr[(size_t)i * 128 + co]);
    float4 yr1 = *reinterpret_cast<const float4*>(&g_yr[(size_t)i * 128 + co + 4]);
    float4 bb0 = *reinterpret_cast<const float4*>(&bias[co]);
    float4 bb1 = *reinterpret_cast<const float4*>(&bias[co + 4]);
    float r[8];
    r[0] = fmaxf(fmaf(a[0] + b[0], inv, yr0.x + bb0.x), 0.0f);
    r[1] = fmaxf(fmaf(a[1] + b[1], inv, yr0.y + bb0.y), 0.0f);
    r[2] = fmaxf(fmaf(a[2] + b[2], inv, yr0.z + bb0.z), 0.0f);
    r[3] = fmaxf(fmaf(a[3] + b[3], inv, yr0.w + bb0.w), 0.0f);
    r[4] = fmaxf(fmaf(a[4] + b[4], inv, yr1.x + bb1.x), 0.0f);
    r[5] = fmaxf(fmaf(a[5] + b[5], inv, yr1.y + bb1.y), 0.0f);
    r[6] = fmaxf(fmaf(a[6] + b[6], inv, yr1.z + bb1.z), 0.0f);
    r[7] = fmaxf(fmaf(a[7] + b[7], inv, yr1.w + bb1.w), 0.0f);
    if (!do_pool) {
        float* p = &Hout[(size_t)i * HID + co];
        *reinterpret_cast<float4*>(p)     = make_float4(r[0], r[1], r[2], r[3]);
        *reinterpret_cast<float4*>(p + 4) = make_float4(r[4], r[5], r[6], r[7]);
    } else {
        int g = batch[i];
        float* p = &pooled[(size_t)g * HID + co];
#pragma unroll
        for (int q = 0; q < 8; q++) atomicAdd(p + q, r[q]);
    }
}

// ---------------- final divide ----------------
__global__ void div_kernel(float* __restrict__ pooled) {
    int idx = blockIdx.x * blockDim.x + threadIdx.x;
    if (idx < N_GRAPHS * HID) {
        int g = idx >> 7;
        pooled[idx] *= 1.0f / fmaxf((float)g_counts[g], 1.0f);
    }
}

// ---------------- launch ----------------
extern "C" void kernel_launch(void* const* d_in, const int* in_sizes, int n_in,
                              void* d_out, int out_size) {
    const float* x     = (const float*)d_in[0];
    const int*   ei    = (const int*)d_in[1];
    const int*   batch = (const int*)d_in[2];
    const float* W1l = (const float*)d_in[3];
    const float* W1r = (const float*)d_in[4];
    const float* b1  = (const float*)d_in[5];
    const float* W2l = (const float*)d_in[6];
    const float* W2r = (const float*)d_in[7];
    const float* b2  = (const float*)d_in[8];
    const float* W3l = (const float*)d_in[9];
    const float* W3r = (const float*)d_in[10];
    const float* b3  = (const float*)d_in[11];
    float* pooled = (float*)d_out;

    float *h0, *h1;
    __nv_bfloat16 *whi, *wlo;
    cudaGetSymbolAddress((void**)&h0,  g_h0);
    cudaGetSymbolAddress((void**)&h1,  g_h1);
    cudaGetSymbolAddress((void**)&whi, g_whi);
    cudaGetSymbolAddress((void**)&wlo, g_wlo);

    cudaFuncSetAttribute(gemm_tc_kernel, cudaFuncAttributeMaxDynamicSharedMemorySize, SM_TOT);

    const int nscan = (N_NODES + 1023) / 1024;   // 49

    init_kernel<<<256, 256>>>(pooled, W1l, W1r, W2l, W2r, W3l, W3r);
    hist_kernel<<<(N_EDGES + 255) / 256, 256>>>(ei, batch);
    scanA_kernel<<<nscan, 1024>>>();
    scanC_kernel<<<nscan, 1024>>>(nscan);
    csr_kernel<<<(N_EDGES + 255) / 256, 256>>>(ei);

    const int ntiles = (N_NODES + 127) / 128;
    const int cblocks = (N_NODES * 16 + 255) / 256;

    // layer 1
    gemm_tc_kernel<<<ntiles, 256, SM_TOT>>>(x, whi, wlo);
    combine_kernel<<<cblocks, 256>>>(b1, h0, nullptr, nullptr, 0);
    // layer 2
    gemm_tc_kernel<<<ntiles, 256, SM_TOT>>>(h0, whi + 256 * 128, wlo + 256 * 128);
    combine_kernel<<<cblocks, 256>>>(b2, h1, nullptr, nullptr, 0);
    // layer 3 (pool fused)
    gemm_tc_kernel<<<ntiles, 256, SM_TOT>>>(h1, whi + 2 * 256 * 128, wlo + 2 * 256 * 128);
    combine_kernel<<<cblocks, 256>>>(b3, nullptr, batch, pooled, 1);

    div_kernel<<<(N_GRAPHS * HID + 255) / 256, 256>>>(pooled);
}

// round 9
// speedup vs baseline: 1.0467x; 1.0467x over previous
#include <cuda_runtime.h>
#include <cuda_bf16.h>
#include <cuda_fp16.h>
#include <cstdint>

#define N_NODES  50000
#define N_EDGES  800000
#define HID      128
#define N_GRAPHS 512

// ---------------- scratch ----------------
__device__ int   g_deg[N_NODES];
__device__ int   g_tmp_incl[N_NODES];
__device__ int   g_bsum[64];
__device__ int   g_cursor[N_NODES];
__device__ int   g_row_start[N_NODES + 1];
__device__ int   g_counts[N_GRAPHS];
__device__ int   g_csr_src[N_EDGES];
__device__ float g_inv_deg[N_NODES];

__device__ __half g_ylh[(size_t)N_NODES * 128];   // left-branch product, fp16 (gathered)
__device__ float  g_yr[(size_t)N_NODES * 128];    // right-branch product, fp32 (own row)

// bf16 hi/lo activation buffers (split precision)
__device__ __nv_bfloat16 g_xhi[(size_t)N_NODES * HID];
__device__ __nv_bfloat16 g_xlo[(size_t)N_NODES * HID];
__device__ __nv_bfloat16 g_hhi0[(size_t)N_NODES * HID];
__device__ __nv_bfloat16 g_hlo0[(size_t)N_NODES * HID];
__device__ __nv_bfloat16 g_hhi1[(size_t)N_NODES * HID];
__device__ __nv_bfloat16 g_hlo1[(size_t)N_NODES * HID];
// converted weights: [layer][256 rows (Wl then Wr)][128 k]
__device__ __nv_bfloat16 g_whi[3 * 256 * 128];
__device__ __nv_bfloat16 g_wlo[3 * 256 * 128];

// ---------------- init ----------------
__global__ void init_kernel(float* __restrict__ pooled) {
    int i = blockIdx.x * blockDim.x + threadIdx.x;
    int stride = gridDim.x * blockDim.x;
    for (int j = i; j < N_NODES; j += stride) g_deg[j] = 0;
    for (int j = i; j < N_GRAPHS; j += stride) g_counts[j] = 0;
    for (int j = i; j < N_GRAPHS * HID; j += stride) pooled[j] = 0.0f;
}

// ---------------- histograms: 4 edges/thread (int4) ----------------
__global__ void hist_kernel(const int* __restrict__ ei, const int* __restrict__ batch) {
    int q = blockIdx.x * blockDim.x + threadIdx.x;
    if (q < N_EDGES / 4) {
        int4 d = *reinterpret_cast<const int4*>(&ei[N_EDGES + q * 4]);
        atomicAdd(&g_deg[d.x], 1);
        atomicAdd(&g_deg[d.y], 1);
        atomicAdd(&g_deg[d.z], 1);
        atomicAdd(&g_deg[d.w], 1);
    }
    if (q < N_NODES / 4) {
        int4 b = *reinterpret_cast<const int4*>(&batch[q * 4]);
        atomicAdd(&g_counts[b.x], 1);
        atomicAdd(&g_counts[b.y], 1);
        atomicAdd(&g_counts[b.z], 1);
        atomicAdd(&g_counts[b.w], 1);
    }
}

// ---------------- scan A: per-block inclusive scans of deg ----------------
__global__ __launch_bounds__(1024)
void scanA_kernel() {
    __shared__ int wsum[32];
    const int t = threadIdx.x, lane = t & 31, wid = t >> 5;
    const int i = blockIdx.x * 1024 + t;
    int v = (i < N_NODES) ? g_deg[i] : 0;
    int x = v;
#pragma unroll
    for (int o = 1; o < 32; o <<= 1) {
        int y = __shfl_up_sync(0xffffffffu, x, o);
        if (lane >= o) x += y;
    }
    if (lane == 31) wsum[wid] = x;
    __syncthreads();
    if (wid == 0) {
        int w = wsum[lane];
#pragma unroll
        for (int o = 1; o < 32; o <<= 1) {
            int y = __shfl_up_sync(0xffffffffu, w, o);
            if (lane >= o) w += y;
        }
        wsum[lane] = w;
    }
    __syncthreads();
    int incl = x + (wid ? wsum[wid - 1] : 0);
    if (i < N_NODES) g_tmp_incl[i] = incl;
    if (t == 1023) g_bsum[blockIdx.x] = incl;
}

// ---------------- scan C: redundant 64-wide block-sum scan + finalize ----------------
__global__ __launch_bounds__(1024)
void scanC_kernel(int nblocks) {
    __shared__ int s[64];
    const int t = threadIdx.x;
    if (t < 64) s[t] = (t < nblocks) ? g_bsum[t] : 0;
    __syncthreads();
#pragma unroll
    for (int o = 1; o < 64; o <<= 1) {
        int v = 0;
        if (t < 64 && t >= o) v = s[t - o];
        __syncthreads();
        if (t < 64) s[t] += v;
        __syncthreads();
    }
    const int i = blockIdx.x * 1024 + t;
    if (i >= N_NODES) return;
    int boff = blockIdx.x ? s[blockIdx.x - 1] : 0;
    int d = g_deg[i];
    int rs = boff + g_tmp_incl[i] - d;
    g_row_start[i] = rs;
    g_cursor[i]    = rs;
    g_inv_deg[i]   = 1.0f / fmaxf((float)d, 1.0f);
    if (i == N_NODES - 1) g_row_start[N_NODES] = rs + d;
}

// ---------------- CSR fill: 4 edges/thread (int4) ----------------
__global__ void csr_kernel(const int* __restrict__ ei) {
    int q = blockIdx.x * blockDim.x + threadIdx.x;
    if (q >= N_EDGES / 4) return;
    int4 s = *reinterpret_cast<const int4*>(&ei[q * 4]);
    int4 d = *reinterpret_cast<const int4*>(&ei[N_EDGES + q * 4]);
    int p0 = atomicAdd(&g_cursor[d.x], 1);
    int p1 = atomicAdd(&g_cursor[d.y], 1);
    int p2 = atomicAdd(&g_cursor[d.z], 1);
    int p3 = atomicAdd(&g_cursor[d.w], 1);
    g_csr_src[p0] = s.x;
    g_csr_src[p1] = s.y;
    g_csr_src[p2] = s.z;
    g_csr_src[p3] = s.w;
}

// ---------------- split helpers ----------------
__device__ __forceinline__ void split1(float v, __nv_bfloat16& hi, __nv_bfloat16& lo) {
    hi = __float2bfloat16_rn(v);
    lo = __float2bfloat16_rn(v - __bfloat162float(hi));
}

// ---------------- convert x and weights -> bf16 hi/lo (merged) ----------------
__global__ void conv_kernel(const float* __restrict__ x,
                            const float* __restrict__ W1l, const float* __restrict__ W1r,
                            const float* __restrict__ W2l, const float* __restrict__ W2r,
                            const float* __restrict__ W3l, const float* __restrict__ W3r) {
    int i = blockIdx.x * blockDim.x + threadIdx.x;   // one float4 of x per thread
    if (i < N_NODES * HID / 4) {
        float4 v = *reinterpret_cast<const float4*>(&x[(size_t)i * 4]);
        __nv_bfloat16 h0, h1, h2, h3, l0, l1, l2, l3;
        split1(v.x, h0, l0); split1(v.y, h1, l1); split1(v.z, h2, l2); split1(v.w, h3, l3);
        __nv_bfloat16* ph = &g_xhi[(size_t)i * 4];
        __nv_bfloat16* pl = &g_xlo[(size_t)i * 4];
        ph[0] = h0; ph[1] = h1; ph[2] = h2; ph[3] = h3;
        pl[0] = l0; pl[1] = l1; pl[2] = l2; pl[3] = l3;
    }
    if (i < 3 * 256 * 128) {
        int layer = i / (256 * 128);
        int rem = i % (256 * 128);
        int n = rem / 128, k = rem % 128;
        const float* Wp;
        if (layer == 0) Wp = (n < 128) ? W1l : W1r;
        else if (layer == 1) Wp = (n < 128) ? W2l : W2r;
        else Wp = (n < 128) ? W3l : W3r;
        float v = Wp[(n & 127) * 128 + k];
        __nv_bfloat16 hi, lo;
        split1(v, hi, lo);
        g_whi[i] = hi;
        g_wlo[i] = lo;
    }
}

// ---------------- mma.sync bf16 GEMM: [yl(fp16) | yr(fp32)] = A @ [Wl^T | Wr^T] ----------------
// bf16x2 split: D = Ahi@Bhi + Ahi@Blo + Alo@Bhi (fp32 accum)
#define ASTR 136                       // smem row stride in bf16 elems (conflict-free)
static const int SM_AHI = 0;
static const int SM_ALO = SM_AHI + 128 * ASTR * 2;   // 34816
static const int SM_BHI = SM_ALO + 128 * ASTR * 2;   // 69632
static const int SM_BLO = SM_BHI + 256 * ASTR * 2;   // 139264
static const int SM_TOT = SM_BLO + 256 * ASTR * 2;   // 208896

__device__ __forceinline__ void mma16816(float* c, const uint32_t* a, const uint32_t* b) {
    asm volatile(
        "mma.sync.aligned.m16n8k16.row.col.f32.bf16.bf16.f32 "
        "{%0,%1,%2,%3}, {%4,%5,%6,%7}, {%8,%9}, {%0,%1,%2,%3};"
        : "+f"(c[0]), "+f"(c[1]), "+f"(c[2]), "+f"(c[3])
        : "r"(a[0]), "r"(a[1]), "r"(a[2]), "r"(a[3]), "r"(b[0]), "r"(b[1]));
}

__global__ __launch_bounds__(256, 1)
void gemm_tc_kernel(const __nv_bfloat16* __restrict__ Ahi, const __nv_bfloat16* __restrict__ Alo,
                    const __nv_bfloat16* __restrict__ Whi, const __nv_bfloat16* __restrict__ Wlo) {
    extern __shared__ char smem[];
    const int t = threadIdx.x;
    const int row0 = blockIdx.x * 128;

    // ---- stage A (128x128 bf16 hi/lo) ----
#pragma unroll
    for (int i = t; i < 128 * 16; i += 256) {
        int r = i >> 4, k = (i & 15) * 8;
        int row = row0 + r;
        uint4 vh = make_uint4(0, 0, 0, 0), vl = make_uint4(0, 0, 0, 0);
        if (row < N_NODES) {
            vh = *reinterpret_cast<const uint4*>(&Ahi[(size_t)row * HID + k]);
            vl = *reinterpret_cast<const uint4*>(&Alo[(size_t)row * HID + k]);
        }
        *reinterpret_cast<uint4*>(smem + SM_AHI + (r * ASTR + k) * 2) = vh;
        *reinterpret_cast<uint4*>(smem + SM_ALO + (r * ASTR + k) * 2) = vl;
    }
    // ---- stage B (256x128 bf16 hi/lo) ----
#pragma unroll
    for (int i = t; i < 256 * 16; i += 256) {
        int n = i >> 4, k = (i & 15) * 8;
        *reinterpret_cast<uint4*>(smem + SM_BHI + (n * ASTR + k) * 2) =
            *reinterpret_cast<const uint4*>(&Whi[n * HID + k]);
        *reinterpret_cast<uint4*>(smem + SM_BLO + (n * ASTR + k) * 2) =
            *reinterpret_cast<const uint4*>(&Wlo[n * HID + k]);
    }
    __syncthreads();

    const int wid = t >> 5, lane = t & 31;
    const int g = lane >> 2, tig = lane & 3;
    const int wm = (wid & 1) * 64;        // warp M offset (2 warps in M)
    const int wn = (wid >> 1) * 64;       // warp N offset (4 warps in N)

    float acc[4][8][4];
#pragma unroll
    for (int a = 0; a < 4; a++)
#pragma unroll
        for (int b = 0; b < 8; b++)
#pragma unroll
            for (int c = 0; c < 4; c++) acc[a][b][c] = 0.0f;

    for (int ks = 0; ks < 8; ks++) {
        const int k0 = ks * 16 + tig * 2;
        uint32_t ah[4][4], al[4][4];
#pragma unroll
        for (int mt = 0; mt < 4; mt++) {
            int base = ((wm + mt * 16 + g) * ASTR + k0) * 2;
            ah[mt][0] = *reinterpret_cast<const uint32_t*>(smem + SM_AHI + base);
            ah[mt][1] = *reinterpret_cast<const uint32_t*>(smem + SM_AHI + base + 8 * ASTR * 2);
            ah[mt][2] = *reinterpret_cast<const uint32_t*>(smem + SM_AHI + base + 16);
            ah[mt][3] = *reinterpret_cast<const uint32_t*>(smem + SM_AHI + base + 8 * ASTR * 2 + 16);
            al[mt][0] = *reinterpret_cast<const uint32_t*>(smem + SM_ALO + base);
            al[mt][1] = *reinterpret_cast<const uint32_t*>(smem + SM_ALO + base + 8 * ASTR * 2);
            al[mt][2] = *reinterpret_cast<const uint32_t*>(smem + SM_ALO + base + 16);
            al[mt][3] = *reinterpret_cast<const uint32_t*>(smem + SM_ALO + base + 8 * ASTR * 2 + 16);
        }
#pragma unroll
        for (int nh = 0; nh < 2; nh++) {
            uint32_t bh[4][2], bl[4][2];
#pragma unroll
            for (int nt = 0; nt < 4; nt++) {
                int base = ((wn + nh * 32 + nt * 8 + g) * ASTR + k0) * 2;
                bh[nt][0] = *reinterpret_cast<const uint32_t*>(smem + SM_BHI + base);
                bh[nt][1] = *reinterpret_cast<const uint32_t*>(smem + SM_BHI + base + 16);
                bl[nt][0] = *reinterpret_cast<const uint32_t*>(smem + SM_BLO + base);
                bl[nt][1] = *reinterpret_cast<const uint32_t*>(smem + SM_BLO + base + 16);
            }
#pragma unroll
            for (int mt = 0; mt < 4; mt++)
#pragma unroll
                for (int nt = 0; nt < 4; nt++) {
                    float* c = acc[mt][nh * 4 + nt];
                    mma16816(c, ah[mt], bh[nt]);
                    mma16816(c, ah[mt], bl[nt]);
                    mma16816(c, al[mt], bh[nt]);
                }
        }
    }

    // ---- epilogue: cols [0,128) -> fp16 g_ylh ; cols [128,256) -> fp32 g_yr ----
#pragma unroll
    for (int mt = 0; mt < 4; mt++)
#pragma unroll
        for (int nt = 0; nt < 8; nt++) {
            int row = row0 + wm + mt * 16 + g;
            int col = wn + nt * 8 + tig * 2;
            float* c = acc[mt][nt];
            if (col < 128) {
                if (row < N_NODES)
                    *reinterpret_cast<__half2*>(&g_ylh[(size_t)row * 128 + col]) =
                        __floats2half2_rn(c[0], c[1]);
                if (row + 8 < N_NODES)
                    *reinterpret_cast<__half2*>(&g_ylh[(size_t)(row + 8) * 128 + col]) =
                        __floats2half2_rn(c[2], c[3]);
            } else {
                int cr = col - 128;
                if (row < N_NODES)
                    *reinterpret_cast<float2*>(&g_yr[(size_t)row * 128 + cr]) = make_float2(c[0], c[1]);
                if (row + 8 < N_NODES)
                    *reinterpret_cast<float2*>(&g_yr[(size_t)(row + 8) * 128 + cr]) = make_float2(c[2], c[3]);
            }
        }
}

// ---------------- combine: 32 lanes/node, 4-chain unroll, uint2 fp16 gathers ----------------
__device__ __forceinline__ void acc_half4(float4& acc, const __half* p) {
    uint2 u = *reinterpret_cast<const uint2*>(p);
    float2 f0 = __half22float2(*reinterpret_cast<__half2*>(&u.x));
    float2 f1 = __half22float2(*reinterpret_cast<__half2*>(&u.y));
    acc.x += f0.x; acc.y += f0.y; acc.z += f1.x; acc.w += f1.y;
}

__global__ __launch_bounds__(256)
void combine_kernel(const float* __restrict__ bias,
                    __nv_bfloat16* __restrict__ Hhi, __nv_bfloat16* __restrict__ Hlo,
                    const int* __restrict__ batch, float* __restrict__ pooled,
                    int do_pool) {
    int i = (blockIdx.x * blockDim.x + threadIdx.x) >> 5;
    if (i >= N_NODES) return;
    int lane = threadIdx.x & 31;
    int e0 = g_row_start[i], e1 = g_row_start[i + 1];
    float4 acc0 = make_float4(0, 0, 0, 0), acc1 = make_float4(0, 0, 0, 0);
    float4 acc2 = make_float4(0, 0, 0, 0), acc3 = make_float4(0, 0, 0, 0);
    int e = e0;
    const int lo4 = lane * 4;
    for (; e + 4 <= e1; e += 4) {
        int s0 = g_csr_src[e], s1 = g_csr_src[e + 1];
        int s2 = g_csr_src[e + 2], s3 = g_csr_src[e + 3];
        acc_half4(acc0, &g_ylh[(size_t)s0 * 128 + lo4]);
        acc_half4(acc1, &g_ylh[(size_t)s1 * 128 + lo4]);
        acc_half4(acc2, &g_ylh[(size_t)s2 * 128 + lo4]);
        acc_half4(acc3, &g_ylh[(size_t)s3 * 128 + lo4]);
    }
    for (; e < e1; e++) {
        int s0 = g_csr_src[e];
        acc_half4(acc0, &g_ylh[(size_t)s0 * 128 + lo4]);
    }
    acc0.x += acc1.x + acc2.x + acc3.x;
    acc0.y += acc1.y + acc2.y + acc3.y;
    acc0.z += acc1.z + acc2.z + acc3.z;
    acc0.w += acc1.w + acc2.w + acc3.w;

    float inv = g_inv_deg[i];
    float4 yr = *reinterpret_cast<const float4*>(&g_yr[(size_t)i * 128 + lo4]);
    float4 bb = *reinterpret_cast<const float4*>(&bias[lo4]);
    float4 r;
    r.x = fmaxf(fmaf(acc0.x, inv, yr.x + bb.x), 0.0f);
    r.y = fmaxf(fmaf(acc0.y, inv, yr.y + bb.y), 0.0f);
    r.z = fmaxf(fmaf(acc0.z, inv, yr.z + bb.z), 0.0f);
    r.w = fmaxf(fmaf(acc0.w, inv, yr.w + bb.w), 0.0f);
    if (!do_pool) {
        __nv_bfloat16 h0, h1, h2, h3, l0, l1, l2, l3;
        split1(r.x, h0, l0); split1(r.y, h1, l1); split1(r.z, h2, l2); split1(r.w, h3, l3);
        __nv_bfloat16* ph = &Hhi[(size_t)i * HID + lo4];
        __nv_bfloat16* pl = &Hlo[(size_t)i * HID + lo4];
        ph[0] = h0; ph[1] = h1; ph[2] = h2; ph[3] = h3;
        pl[0] = l0; pl[1] = l1; pl[2] = l2; pl[3] = l3;
    } else {
        int g = batch[i];
        float* p = &pooled[(size_t)g * HID + lo4];
        atomicAdd(p + 0, r.x);
        atomicAdd(p + 1, r.y);
        atomicAdd(p + 2, r.z);
        atomicAdd(p + 3, r.w);
    }
}

// ---------------- final divide ----------------
__global__ void div_kernel(float* __restrict__ pooled) {
    int idx = blockIdx.x * blockDim.x + threadIdx.x;
    if (idx < N_GRAPHS * HID) {
        int g = idx >> 7;
        pooled[idx] *= 1.0f / fmaxf((float)g_counts[g], 1.0f);
    }
}

// ---------------- launch ----------------
extern "C" void kernel_launch(void* const* d_in, const int* in_sizes, int n_in,
                              void* d_out, int out_size) {
    const float* x     = (const float*)d_in[0];
    const int*   ei    = (const int*)d_in[1];
    const int*   batch = (const int*)d_in[2];
    const float* W1l = (const float*)d_in[3];
    const float* W1r = (const float*)d_in[4];
    const float* b1  = (const float*)d_in[5];
    const float* W2l = (const float*)d_in[6];
    const float* W2r = (const float*)d_in[7];
    const float* b2  = (const float*)d_in[8];
    const float* W3l = (const float*)d_in[9];
    const float* W3r = (const float*)d_in[10];
    const float* b3  = (const float*)d_in[11];
    float* pooled = (float*)d_out;

    __nv_bfloat16 *xhi, *xlo, *hhi0, *hlo0, *hhi1, *hlo1, *whi, *wlo;
    cudaGetSymbolAddress((void**)&xhi,  g_xhi);
    cudaGetSymbolAddress((void**)&xlo,  g_xlo);
    cudaGetSymbolAddress((void**)&hhi0, g_hhi0);
    cudaGetSymbolAddress((void**)&hlo0, g_hlo0);
    cudaGetSymbolAddress((void**)&hhi1, g_hhi1);
    cudaGetSymbolAddress((void**)&hlo1, g_hlo1);
    cudaGetSymbolAddress((void**)&whi,  g_whi);
    cudaGetSymbolAddress((void**)&wlo,  g_wlo);

    cudaFuncSetAttribute(gemm_tc_kernel, cudaFuncAttributeMaxDynamicSharedMemorySize, SM_TOT);

    const int nscan = (N_NODES + 1023) / 1024;   // 49

    init_kernel<<<256, 256>>>(pooled);
    hist_kernel<<<(N_EDGES / 4 + 255) / 256, 256>>>(ei, batch);
    scanA_kernel<<<nscan, 1024>>>();
    scanC_kernel<<<nscan, 1024>>>(nscan);
    csr_kernel<<<(N_EDGES / 4 + 255) / 256, 256>>>(ei);
    conv_kernel<<<(N_NODES * HID / 4 + 255) / 256, 256>>>(x, W1l, W1r, W2l, W2r, W3l, W3r);

    const int ntiles = (N_NODES + 127) / 128;

    // layer 1
    gemm_tc_kernel<<<ntiles, 256, SM_TOT>>>(xhi, xlo, whi, wlo);
    combine_kernel<<<N_NODES / 8, 256>>>(b1, hhi0, hlo0, nullptr, nullptr, 0);
    // layer 2
    gemm_tc_kernel<<<ntiles, 256, SM_TOT>>>(hhi0, hlo0, whi + 256 * 128, wlo + 256 * 128);
    combine_kernel<<<N_NODES / 8, 256>>>(b2, hhi1, hlo1, nullptr, nullptr, 0);
    // layer 3 (pool fused)
    gemm_tc_kernel<<<ntiles, 256, SM_TOT>>>(hhi1, hlo1, whi + 2 * 256 * 128, wlo + 2 * 256 * 128);
    combine_kernel<<<N_NODES / 8, 256>>>(b3, nullptr, nullptr, batch, pooled, 1);

    div_kernel<<<(N_GRAPHS * HID + 255) / 256, 256>>>(pooled);
}